// round 11
// baseline (speedup 1.0000x reference)
#include <cuda_runtime.h>
#include <cuda_fp16.h>
#include <cstdint>
#include <math.h>

#define B_   2
#define N_   512
#define H_   128
#define NH_  8
#define TJ   64

#define OFF_EOUT   ((size_t)(B_*N_*H_))
#define OFF_SCORES (OFF_EOUT + (size_t)B_*N_*N_*H_)

// ---- smem layout (bytes): double-buffered, 1 CTA/SM ----
#define SM_W    0               // We fp16 (32KB) | Woe fp16 (32KB)
#define WPARTH  32768
#define SM_T0   65536           // tile buf0 16KB fp16
#define SM_T1   81920           // tile buf1 16KB fp16
#define SM_LOG  98304           // logits [8][512] f32 = 16KB
#define SM_Q    114688
#define SM_BE   115200
#define SM_BOE  115712
#define SM_TOTAL 116224

__device__ float g_Q[B_*N_*H_];   // (x@Wq+bq)*0.25
__device__ float g_K[B_*N_*H_];   // x@Wk+bk (= V)
__device__ float g_be[H_];
__device__ float g_boe[H_];
__device__ __align__(16) unsigned char g_Wimg[2*WPARTH];

static __device__ __forceinline__ uint32_t smem_u32(const void* p) {
    uint32_t a;
    asm("{ .reg .u64 t; cvta.to.shared.u64 t, %1; cvt.u32.u64 %0, t; }" : "=r"(a) : "l"(p));
    return a;
}
static __device__ __forceinline__ uint32_t pk2h(__half a, __half b) {
    __half2 t = __halves2half2(a, b);
    return *(uint32_t*)&t;
}
static __device__ __forceinline__ void mma16816(float* c,
        uint32_t a0, uint32_t a1, uint32_t a2, uint32_t a3,
        uint32_t b0, uint32_t b1) {
    asm volatile(
        "mma.sync.aligned.m16n8k16.row.col.f32.f16.f16.f32 "
        "{%0,%1,%2,%3},{%4,%5,%6,%7},{%8,%9},{%0,%1,%2,%3};"
        : "+f"(c[0]), "+f"(c[1]), "+f"(c[2]), "+f"(c[3])
        : "r"(a0), "r"(a1), "r"(a2), "r"(a3), "r"(b0), "r"(b1));
}
#define LDSM4(r, addr) \
    asm volatile("ldmatrix.sync.aligned.m8n8.x4.shared.b16 {%0,%1,%2,%3}, [%4];" \
        : "=r"((r)[0]), "=r"((r)[1]), "=r"((r)[2]), "=r"((r)[3]) : "r"(addr))
// named barrier over the 128 threads of one mi-group (warps with wid&1==mi)
#define BARMI(id) asm volatile("bar.sync %0, 128;" :: "r"(id) : "memory")

// phys byte offset within a tile: row*256 + ((k/8 ^ (row&7))*16) + (k&7)*2
static __device__ __host__ __forceinline__ int tswz(int row, int k) {
    return row*256 + ((((k>>3) ^ (row&7)))<<4) + (k&7)*2;
}

// ---------------------------------------------------------------------------
// prep + qk fused: blocks 0..63 build weight image; blocks 64.. do Q/K rows
// qk: 4 rows per block, each thread computes 2 rows reusing one W load.
// ---------------------------------------------------------------------------
__global__ void prepqk_kernel(const float* __restrict__ We, const float* __restrict__ Woe,
                              const float* __restrict__ be, const float* __restrict__ boe,
                              const float* __restrict__ x,
                              const float* __restrict__ Wq, const float* __restrict__ bq,
                              const float* __restrict__ Wk, const float* __restrict__ bk) {
    if (blockIdx.x < 64) {
        int idx = blockIdx.x * 256 + threadIdx.x;   // 16384
        int c = idx >> 7, k = idx & 127;
        int byt = tswz(c, k);
        *(__half*)(g_Wimg + byt)          = __float2half(We[k*H_ + c]);
        *(__half*)(g_Wimg + WPARTH + byt) = __float2half(Woe[k*H_ + c]);
        if (idx < H_) { g_be[idx] = be[idx]; g_boe[idx] = boe[idx]; }
        return;
    }
    // Q/K: 4 rows per block; thread (rq,c) handles rows row0+2*rq+{0,1}
    __shared__ float xs[4][H_];
    int row0 = (blockIdx.x - 64) * 4;
    int rq = threadIdx.x >> 7, c = threadIdx.x & 127;
    xs[2*rq][c]     = x[(row0 + 2*rq)*H_ + c];
    xs[2*rq + 1][c] = x[(row0 + 2*rq + 1)*H_ + c];
    __syncthreads();
    int r0 = 2*rq;
    float aq0 = bq[c], ak0 = bk[c], aq1 = bq[c], ak1 = bk[c];
#pragma unroll 8
    for (int k = 0; k < H_; ++k) {
        float wq = Wq[k*H_ + c];
        float wk = Wk[k*H_ + c];
        float x0 = xs[r0][k], x1 = xs[r0 + 1][k];
        aq0 = fmaf(x0, wq, aq0);
        ak0 = fmaf(x0, wk, ak0);
        aq1 = fmaf(x1, wq, aq1);
        ak1 = fmaf(x1, wk, ak1);
    }
    g_Q[(row0 + r0)*H_ + c]     = 0.25f * aq0;
    g_K[(row0 + r0)*H_ + c]     = ak0;
    g_Q[(row0 + r0 + 1)*H_ + c] = 0.25f * aq1;
    g_K[(row0 + r0 + 1)*H_ + c] = ak1;
}

// ---------------------------------------------------------------------------
// edge helpers
// ---------------------------------------------------------------------------
static __device__ __forceinline__ void store_tile(char* smem, int buf,
        const float4* pref, int tid) {
#pragma unroll
    for (int l = 0; l < 8; ++l) {
        int u = tid + (l << 8);
        int j = u >> 5, kq = u & 31;
        int k4 = kq << 2;
        int base = buf + tswz(j, k4);
        float4 v = pref[l];
        *(uint2*)(smem + base) = make_uint2(
            pk2h(__float2half(v.x), __float2half(v.y)),
            pk2h(__float2half(v.z), __float2half(v.w)));
    }
}

// C[64x128] += A[64x128] @ B[128x128]^T, fp16 single pass, ldmatrix loads
static __device__ __forceinline__ void gemm_tile(uint32_t sb, uint32_t aB, uint32_t bB,
        uint32_t aR0, uint32_t aR1, int aR7, int khA,
        uint32_t bR0, uint32_t bR1, int bR7, int khB,
        float (&acc)[2][4][4]) {
#pragma unroll
    for (int ks = 0; ks < 8; ++ks) {
        uint32_t swA = (uint32_t)((((ks << 1) | khA) ^ aR7) << 4);
        uint32_t swB = (uint32_t)((((ks << 1) | khB) ^ bR7) << 4);
        uint32_t a0[4], a1[4], b0[4], b1[4];
        LDSM4(a0, sb + aB + aR0 + swA);
        LDSM4(a1, sb + aB + aR1 + swA);
        LDSM4(b0, sb + bB + bR0 + swB);
        LDSM4(b1, sb + bB + bR1 + swB);
        mma16816(acc[0][0], a0[0],a0[1],a0[2],a0[3], b0[0], b0[1]);
        mma16816(acc[0][1], a0[0],a0[1],a0[2],a0[3], b0[2], b0[3]);
        mma16816(acc[0][2], a0[0],a0[1],a0[2],a0[3], b1[0], b1[1]);
        mma16816(acc[0][3], a0[0],a0[1],a0[2],a0[3], b1[2], b1[3]);
        mma16816(acc[1][0], a1[0],a1[1],a1[2],a1[3], b0[0], b0[1]);
        mma16816(acc[1][1], a1[0],a1[1],a1[2],a1[3], b0[2], b0[3]);
        mma16816(acc[1][2], a1[0],a1[1],a1[2],a1[3], b1[0], b1[1]);
        mma16816(acc[1][3], a1[0],a1[1],a1[2],a1[3], b1[2], b1[3]);
    }
}

// ---------------------------------------------------------------------------
// edge: GEMM1 -> inter/logits -> GEMM2, fused mask+softmax. 1 CTA/SM,
// double-buffered e-tile, K prefetch, mi-group named barriers.
// Dependency note: in GEMM1/epi1/GEMM2, warp (mi,ni) only touches bufX rows
// m0..m0+31 of its own mi-group; weights are read-only. So the two syncs
// around epi1 need only span the mi-group (bar.sync 1+mi, 128), and no sync
// is needed between GEMM2 and store_tile (bufY's last reader was GEMM2 of
// the previous iteration, fenced by the end-of-iteration syncthreads).
// ---------------------------------------------------------------------------
__global__ __launch_bounds__(256, 1)
void edge_kernel(const float* __restrict__ e, const float* __restrict__ mask,
                 float* __restrict__ out) {
    extern __shared__ char smem[];
    uint32_t sb = smem_u32(smem);
    int tid = threadIdx.x, wid = tid >> 5, lane = tid & 31;
    int g = lane >> 2, t = lane & 3;
    int mi = wid & 1, ni = wid >> 1;
    int m0 = mi * 32, n0 = ni * 32;
    int row = blockIdx.x, b = row >> 9, i = row & 511;

    {
        const float4* w4 = (const float4*)g_Wimg;
        float4* d4 = (float4*)smem;
#pragma unroll
        for (int u = tid; u < 4096; u += 256) d4[u] = w4[u];
    }
    if (tid < H_) {
        ((float*)(smem + SM_Q))[tid]   = g_Q[(b*N_ + i)*H_ + tid];
        ((float*)(smem + SM_BE))[tid]  = g_be[tid];
        ((float*)(smem + SM_BOE))[tid] = g_boe[tid];
    }

    const float* Kb = g_K + (size_t)b * N_ * H_;
    const float* ebase = e + ((size_t)(b*N_ + i)) * N_ * H_;

    {
        float4 pref[8];
        const float4* esrc = (const float4*)ebase;
#pragma unroll
        for (int l = 0; l < 8; ++l) pref[l] = esrc[tid + (l << 8)];
        store_tile(smem, SM_T0, pref, tid);
    }
    __syncthreads();

    float2 q2[4], be2[4], bo2[4];
#pragma unroll
    for (int nf = 0; nf < 4; ++nf) {
        int c = n0 + nf*8 + 2*t;
        q2[nf]  = *(const float2*)((const float*)(smem + SM_Q)  + c);
        be2[nf] = *(const float2*)((const float*)(smem + SM_BE) + c);
        bo2[nf] = *(const float2*)((const float*)(smem + SM_BOE) + c);
    }

    // ldmatrix lane addressing
    int aRow = m0 + (lane & 15);
    uint32_t aR0 = (uint32_t)(aRow * 256);
    uint32_t aR1 = (uint32_t)((aRow + 16) * 256);
    int aR7 = aRow & 7;
    int khA = lane >> 4;
    int bSel = ((lane >> 4) & 1) * 8 + (lane & 7);
    uint32_t bR0 = (uint32_t)((n0 + bSel) * 256);
    uint32_t bR1 = (uint32_t)((n0 + 16 + bSel) * 256);
    int bR7 = (n0 + bSel) & 7;
    int khB = (lane >> 3) & 1;

    int bufX = SM_T0, bufY = SM_T1;
    float acc[2][4][4];
    float* logit_s = (float*)(smem + SM_LOG);
    int barid = 1 + mi;

    for (int jt = 0; jt < 8; ++jt) {
        int j0 = jt << 6;

        // prefetch next e-tile (stored into bufY after GEMM2)
        float4 pref[8];
        if (jt < 7) {
            const float4* esrc = (const float4*)(ebase + (size_t)(j0 + TJ) * H_);
#pragma unroll
            for (int l = 0; l < 8; ++l) pref[l] = esrc[tid + (l << 8)];
        }
        // prefetch K values for THIS tile's epilogue 1 (independent of GEMM1)
        float2 k0r[2][4], k1r[2][4];
#pragma unroll
        for (int mf = 0; mf < 2; ++mf)
#pragma unroll
            for (int nf = 0; nf < 4; ++nf) {
                int c = n0 + nf*8 + 2*t;
                int jl = m0 + mf*16 + g;
                k0r[mf][nf] = *(const float2*)(Kb + (size_t)(j0 + jl)*H_ + c);
                k1r[mf][nf] = *(const float2*)(Kb + (size_t)(j0 + jl + 8)*H_ + c);
            }

        // ---- GEMM1: Ee = e @ We ----
#pragma unroll
        for (int mf = 0; mf < 2; ++mf)
#pragma unroll
            for (int nf = 0; nf < 4; ++nf)
#pragma unroll
                for (int q = 0; q < 4; ++q) acc[mf][nf][q] = 0.f;
        gemm_tile(sb, bufX, SM_W, aR0, aR1, aR7, khA, bR0, bR1, bR7, khB, acc);
        BARMI(barid);

        // ---- epilogue 1: inter = (Ee+be)*K*Q ; logits ; store inter fp16 ----
        {
            float psum[2][2][2] = {};
#pragma unroll
            for (int mf = 0; mf < 2; ++mf)
#pragma unroll
                for (int nf = 0; nf < 4; ++nf) {
                    int c = n0 + nf*8 + 2*t;
                    int jl = m0 + mf*16 + g;
                    float v0 = (acc[mf][nf][0] + be2[nf].x) * k0r[mf][nf].x * q2[nf].x;
                    float v1 = (acc[mf][nf][1] + be2[nf].y) * k0r[mf][nf].y * q2[nf].y;
                    float v2 = (acc[mf][nf][2] + be2[nf].x) * k1r[mf][nf].x * q2[nf].x;
                    float v3 = (acc[mf][nf][3] + be2[nf].y) * k1r[mf][nf].y * q2[nf].y;
                    psum[mf][0][nf >> 1] += v0 + v1;
                    psum[mf][1][nf >> 1] += v2 + v3;
                    int sw = (((c >> 3) ^ g) << 4) + 4*t;
                    *(uint32_t*)(smem + bufX + jl*256 + sw) =
                        pk2h(__float2half(v0), __float2half(v1));
                    *(uint32_t*)(smem + bufX + (jl + 8)*256 + sw) =
                        pk2h(__float2half(v2), __float2half(v3));
                }
#pragma unroll
            for (int mf = 0; mf < 2; ++mf)
#pragma unroll
                for (int half = 0; half < 2; ++half)
#pragma unroll
                    for (int hl = 0; hl < 2; ++hl) {
                        float s = psum[mf][half][hl];
                        s += __shfl_xor_sync(0xffffffffu, s, 1);
                        s += __shfl_xor_sync(0xffffffffu, s, 2);
                        if (t == 0) {
                            int j = m0 + mf*16 + g + half*8;
                            logit_s[(2*ni + hl)*N_ + j0 + j] = s;
                        }
                    }
        }
        BARMI(barid);

        // ---- GEMM2: e_out = inter @ Woe ----
#pragma unroll
        for (int mf = 0; mf < 2; ++mf)
#pragma unroll
            for (int nf = 0; nf < 4; ++nf)
#pragma unroll
                for (int q = 0; q < 4; ++q) acc[mf][nf][q] = 0.f;
        gemm_tile(sb, bufX, SM_W + WPARTH, aR0, aR1, aR7, khA, bR0, bR1, bR7, khB, acc);

        // no sync needed: bufY's last reader was GEMM2 of previous iteration
        if (jt < 7) store_tile(smem, bufY, pref, tid);

        // ---- epilogue 2: e_out writes ----
#pragma unroll
        for (int mf = 0; mf < 2; ++mf)
#pragma unroll
            for (int nf = 0; nf < 4; ++nf) {
                int c = n0 + nf*8 + 2*t;
                int jl = m0 + mf*16 + g;
                size_t rb = OFF_EOUT + (((size_t)(b*N_ + i))*N_ + j0 + jl)*H_ + c;
                *(float2*)(out + rb) =
                    make_float2(acc[mf][nf][0] + bo2[nf].x, acc[mf][nf][1] + bo2[nf].y);
                *(float2*)(out + rb + 8*H_) =
                    make_float2(acc[mf][nf][2] + bo2[nf].x, acc[mf][nf][3] + bo2[nf].y);
            }
        __syncthreads();

        int tmp = bufX; bufX = bufY; bufY = tmp;
    }

    // ---- fused mask + softmax: warp w handles head w ----
    {
        const float* lg = logit_s + wid * N_;
        const float* mrow = mask + ((size_t)b*N_ + i)*N_;
        float4 vv[4];
        float mx = -3.4e38f;
#pragma unroll
        for (int c4 = 0; c4 < 4; ++c4) {
            int j = c4*128 + lane*4;
            float4 lv = *(const float4*)(lg + j);
            float4 mv = *(const float4*)(mrow + j);
            float4 v = make_float4(lv.x + mv.x, lv.y + mv.y, lv.z + mv.z, lv.w + mv.w);
            vv[c4] = v;
            mx = fmaxf(mx, fmaxf(fmaxf(v.x, v.y), fmaxf(v.z, v.w)));
        }
#pragma unroll
        for (int o = 16; o > 0; o >>= 1)
            mx = fmaxf(mx, __shfl_xor_sync(0xffffffffu, mx, o));
        float sum = 0.f;
#pragma unroll
        for (int c4 = 0; c4 < 4; ++c4) {
            vv[c4].x = expf(vv[c4].x - mx);
            vv[c4].y = expf(vv[c4].y - mx);
            vv[c4].z = expf(vv[c4].z - mx);
            vv[c4].w = expf(vv[c4].w - mx);
            sum += vv[c4].x + vv[c4].y + vv[c4].z + vv[c4].w;
        }
#pragma unroll
        for (int o = 16; o > 0; o >>= 1)
            sum += __shfl_xor_sync(0xffffffffu, sum, o);
        float inv = 1.f / sum;
        float* orow = out + OFF_SCORES + (((size_t)(b*NH_ + wid)*N_ + i) << 9);
#pragma unroll
        for (int c4 = 0; c4 < 4; ++c4) {
            int j = c4*128 + lane*4;
            *(float4*)(orow + j) = make_float4(vv[c4].x*inv, vv[c4].y*inv,
                                               vv[c4].z*inv, vv[c4].w*inv);
        }
    }
}

// ---------------------------------------------------------------------------
// out: att = scores @ V(=K) ; x_out = att @ Woh + boh.
// 4 i-rows per block; each thread loads K once, FMAs for all 4 i rows.
// ---------------------------------------------------------------------------
__global__ __launch_bounds__(512)
void out_kernel(const float* __restrict__ Woh, const float* __restrict__ boh,
                float* __restrict__ out) {
    extern __shared__ char osm[];
    float* sc    = (float*)osm;                    // [4][NH][N] = 64KB
    float* red   = (float*)(osm + 65536);          // [4][512]   = 8KB
    float* att_s = (float*)(osm + 65536 + 8192);   // [4][128]   = 2KB
    int blk = blockIdx.x;
    int b = blk >> 7, i0 = (blk & 127) << 2;
    int tid = threadIdx.x;

    const float* sp = out + OFF_SCORES;
    for (int u = tid; u < 4*NH_*N_; u += 512) {
        int il = u >> 12, h = (u >> 9) & 7, j = u & 511;
        sc[u] = sp[(((size_t)(b*NH_ + h)*N_ + i0 + il) << 9) + j];
    }
    __syncthreads();

    int c = tid & 127, t2 = tid >> 7;              // t2: j quarter (0..3)
    int h = c >> 4;
    const float* kp = g_K + (((size_t)b*N_) + t2*128)*H_ + c;
    const float* s0 = sc + 0*NH_*N_ + h*N_ + t2*128;
    const float* s1 = sc + 1*NH_*N_ + h*N_ + t2*128;
    const float* s2 = sc + 2*NH_*N_ + h*N_ + t2*128;
    const float* s3 = sc + 3*NH_*N_ + h*N_ + t2*128;
    float a0 = 0.f, a1 = 0.f, a2 = 0.f, a3 = 0.f;
#pragma unroll 8
    for (int j = 0; j < 128; ++j) {
        float kv = kp[(size_t)j*H_];
        a0 = fmaf(s0[j], kv, a0);
        a1 = fmaf(s1[j], kv, a1);
        a2 = fmaf(s2[j], kv, a2);
        a3 = fmaf(s3[j], kv, a3);
    }
    red[0*512 + tid] = a0;
    red[1*512 + tid] = a1;
    red[2*512 + tid] = a2;
    red[3*512 + tid] = a3;
    __syncthreads();
    {
        int il = tid >> 7, cc = tid & 127;         // 512 threads = 4 il x 128 c
        att_s[il*H_ + cc] = red[il*512 + cc] + red[il*512 + 128 + cc] +
                            red[il*512 + 256 + cc] + red[il*512 + 384 + cc];
    }
    __syncthreads();
    {
        int il = tid >> 7, cc = tid & 127;
        float o = boh[cc];
        const float* as = att_s + il*H_;
#pragma unroll 8
        for (int k = 0; k < H_; ++k)
            o = fmaf(as[k], Woh[k*H_ + cc], o);
        out[((size_t)(b*N_) + i0 + il)*H_ + cc] = o;
    }
}
#define OUT_SMEM (65536 + 8192 + 2048)

// ---------------------------------------------------------------------------
extern "C" void kernel_launch(void* const* d_in, const int* in_sizes, int n_in,
                              void* d_out, int out_size) {
    const float* x    = (const float*)d_in[0];
    const float* e    = (const float*)d_in[1];
    const float* mask = (const float*)d_in[2];
    const float* Wq   = (const float*)d_in[3];
    const float* bq   = (const float*)d_in[4];
    const float* Wk   = (const float*)d_in[5];
    const float* bk   = (const float*)d_in[6];
    const float* We   = (const float*)d_in[7];
    const float* be   = (const float*)d_in[8];
    const float* Woh  = (const float*)d_in[9];
    const float* boh  = (const float*)d_in[10];
    const float* Woe  = (const float*)d_in[11];
    const float* boe  = (const float*)d_in[12];
    float* out = (float*)d_out;

    cudaFuncSetAttribute(edge_kernel, cudaFuncAttributeMaxDynamicSharedMemorySize, SM_TOTAL);
    cudaFuncSetAttribute(out_kernel, cudaFuncAttributeMaxDynamicSharedMemorySize, OUT_SMEM);

    prepqk_kernel<<<64 + B_*N_/4, 256>>>(We, Woe, be, boe, x, Wq, bq, Wk, bk);
    edge_kernel<<<B_*N_, 256, SM_TOTAL>>>(e, mask, out);
    out_kernel<<<B_*N_/4, 512, OUT_SMEM>>>(Woh, boh, out);
}

// round 13
// speedup vs baseline: 1.0153x; 1.0153x over previous
#include <cuda_runtime.h>
#include <cuda_fp16.h>
#include <cstdint>
#include <math.h>

#define B_   2
#define N_   512
#define H_   128
#define NH_  8
#define TJ   64

#define OFF_EOUT   ((size_t)(B_*N_*H_))
#define OFF_SCORES (OFF_EOUT + (size_t)B_*N_*N_*H_)

// ---- smem layout (bytes): double-buffered, 1 CTA/SM ----
#define SM_W    0               // We fp16 (32KB) | Woe fp16 (32KB)
#define WPARTH  32768
#define SM_T0   65536           // tile buf0 16KB fp16
#define SM_T1   81920           // tile buf1 16KB fp16
#define SM_LOG  98304           // logits [8][512] f32 = 16KB
#define SM_Q    114688
#define SM_BE   115200
#define SM_BOE  115712
#define SM_TOTAL 116224

__device__ float g_Q[B_*N_*H_];   // (x@Wq+bq)*0.25
__device__ float g_K[B_*N_*H_];   // x@Wk+bk (= V)
__device__ float g_be[H_];
__device__ float g_boe[H_];
__device__ __align__(16) unsigned char g_Wimg[2*WPARTH];

static __device__ __forceinline__ uint32_t smem_u32(const void* p) {
    uint32_t a;
    asm("{ .reg .u64 t; cvta.to.shared.u64 t, %1; cvt.u32.u64 %0, t; }" : "=r"(a) : "l"(p));
    return a;
}
static __device__ __forceinline__ uint32_t pk2h(__half a, __half b) {
    __half2 t = __halves2half2(a, b);
    return *(uint32_t*)&t;
}
static __device__ __forceinline__ void mma16816(float* c,
        uint32_t a0, uint32_t a1, uint32_t a2, uint32_t a3,
        uint32_t b0, uint32_t b1) {
    asm volatile(
        "mma.sync.aligned.m16n8k16.row.col.f32.f16.f16.f32 "
        "{%0,%1,%2,%3},{%4,%5,%6,%7},{%8,%9},{%0,%1,%2,%3};"
        : "+f"(c[0]), "+f"(c[1]), "+f"(c[2]), "+f"(c[3])
        : "r"(a0), "r"(a1), "r"(a2), "r"(a3), "r"(b0), "r"(b1));
}
#define LDSM4(r, addr) \
    asm volatile("ldmatrix.sync.aligned.m8n8.x4.shared.b16 {%0,%1,%2,%3}, [%4];" \
        : "=r"((r)[0]), "=r"((r)[1]), "=r"((r)[2]), "=r"((r)[3]) : "r"(addr))

// phys byte offset within a tile: row*256 + ((k/8 ^ (row&7))*16) + (k&7)*2
static __device__ __host__ __forceinline__ int tswz(int row, int k) {
    return row*256 + ((((k>>3) ^ (row&7)))<<4) + (k&7)*2;
}

// ---------------------------------------------------------------------------
// prep + qk fused: blocks 0..63 build weight image; blocks 64.. do Q/K rows
// qk: 2 rows per block (r10-proven variant).
// ---------------------------------------------------------------------------
__global__ void prepqk_kernel(const float* __restrict__ We, const float* __restrict__ Woe,
                              const float* __restrict__ be, const float* __restrict__ boe,
                              const float* __restrict__ x,
                              const float* __restrict__ Wq, const float* __restrict__ bq,
                              const float* __restrict__ Wk, const float* __restrict__ bk) {
    if (blockIdx.x < 64) {
        int idx = blockIdx.x * 256 + threadIdx.x;   // 16384
        int c = idx >> 7, k = idx & 127;
        int byt = tswz(c, k);
        *(__half*)(g_Wimg + byt)          = __float2half(We[k*H_ + c]);
        *(__half*)(g_Wimg + WPARTH + byt) = __float2half(Woe[k*H_ + c]);
        if (idx < H_) { g_be[idx] = be[idx]; g_boe[idx] = boe[idx]; }
        return;
    }
    // Q/K: 2 rows per block (256 threads)
    __shared__ float xs[2][H_];
    int row0 = (blockIdx.x - 64) * 2;
    int rl = threadIdx.x >> 7, c = threadIdx.x & 127;
    int row = row0 + rl;
    xs[rl][c] = x[row*H_ + c];
    __syncthreads();
    float aq = bq[c], ak = bk[c];
#pragma unroll 8
    for (int k = 0; k < H_; ++k) {
        float xv = xs[rl][k];
        aq = fmaf(xv, Wq[k*H_ + c], aq);
        ak = fmaf(xv, Wk[k*H_ + c], ak);
    }
    g_Q[row*H_ + c] = 0.25f * aq;
    g_K[row*H_ + c] = ak;
}

// ---------------------------------------------------------------------------
// edge helpers
// ---------------------------------------------------------------------------
static __device__ __forceinline__ void store_tile(char* smem, int buf,
        const float4* pref, int tid) {
#pragma unroll
    for (int l = 0; l < 8; ++l) {
        int u = tid + (l << 8);
        int j = u >> 5, kq = u & 31;
        int k4 = kq << 2;
        int base = buf + tswz(j, k4);
        float4 v = pref[l];
        *(uint2*)(smem + base) = make_uint2(
            pk2h(__float2half(v.x), __float2half(v.y)),
            pk2h(__float2half(v.z), __float2half(v.w)));
    }
}

// C[64x128] += A[64x128] @ B[128x128]^T, fp16 single pass, ldmatrix loads
static __device__ __forceinline__ void gemm_tile(uint32_t sb, uint32_t aB, uint32_t bB,
        uint32_t aR0, uint32_t aR1, int aR7, int khA,
        uint32_t bR0, uint32_t bR1, int bR7, int khB,
        float (&acc)[2][4][4]) {
#pragma unroll
    for (int ks = 0; ks < 8; ++ks) {
        uint32_t swA = (uint32_t)((((ks << 1) | khA) ^ aR7) << 4);
        uint32_t swB = (uint32_t)((((ks << 1) | khB) ^ bR7) << 4);
        uint32_t a0[4], a1[4], b0[4], b1[4];
        LDSM4(a0, sb + aB + aR0 + swA);
        LDSM4(a1, sb + aB + aR1 + swA);
        LDSM4(b0, sb + bB + bR0 + swB);
        LDSM4(b1, sb + bB + bR1 + swB);
        mma16816(acc[0][0], a0[0],a0[1],a0[2],a0[3], b0[0], b0[1]);
        mma16816(acc[0][1], a0[0],a0[1],a0[2],a0[3], b0[2], b0[3]);
        mma16816(acc[0][2], a0[0],a0[1],a0[2],a0[3], b1[0], b1[1]);
        mma16816(acc[0][3], a0[0],a0[1],a0[2],a0[3], b1[2], b1[3]);
        mma16816(acc[1][0], a1[0],a1[1],a1[2],a1[3], b0[0], b0[1]);
        mma16816(acc[1][1], a1[0],a1[1],a1[2],a1[3], b0[2], b0[3]);
        mma16816(acc[1][2], a1[0],a1[1],a1[2],a1[3], b1[0], b1[1]);
        mma16816(acc[1][3], a1[0],a1[1],a1[2],a1[3], b1[2], b1[3]);
    }
}

// ---------------------------------------------------------------------------
// edge: GEMM1 -> inter/logits -> GEMM2, fused mask+softmax. 1 CTA/SM,
// double-buffered e-tile, K prefetch. (r10-proven sync structure.)
// ---------------------------------------------------------------------------
__global__ __launch_bounds__(256, 1)
void edge_kernel(const float* __restrict__ e, const float* __restrict__ mask,
                 float* __restrict__ out) {
    extern __shared__ char smem[];
    uint32_t sb = smem_u32(smem);
    int tid = threadIdx.x, wid = tid >> 5, lane = tid & 31;
    int g = lane >> 2, t = lane & 3;
    int mi = wid & 1, ni = wid >> 1;
    int m0 = mi * 32, n0 = ni * 32;
    int row = blockIdx.x, b = row >> 9, i = row & 511;

    {
        const float4* w4 = (const float4*)g_Wimg;
        float4* d4 = (float4*)smem;
#pragma unroll
        for (int u = tid; u < 4096; u += 256) d4[u] = w4[u];
    }
    if (tid < H_) {
        ((float*)(smem + SM_Q))[tid]   = g_Q[(b*N_ + i)*H_ + tid];
        ((float*)(smem + SM_BE))[tid]  = g_be[tid];
        ((float*)(smem + SM_BOE))[tid] = g_boe[tid];
    }

    const float* Kb = g_K + (size_t)b * N_ * H_;
    const float* ebase = e + ((size_t)(b*N_ + i)) * N_ * H_;

    {
        float4 pref[8];
        const float4* esrc = (const float4*)ebase;
#pragma unroll
        for (int l = 0; l < 8; ++l) pref[l] = esrc[tid + (l << 8)];
        store_tile(smem, SM_T0, pref, tid);
    }
    __syncthreads();

    float2 q2[4], be2[4], bo2[4];
#pragma unroll
    for (int nf = 0; nf < 4; ++nf) {
        int c = n0 + nf*8 + 2*t;
        q2[nf]  = *(const float2*)((const float*)(smem + SM_Q)  + c);
        be2[nf] = *(const float2*)((const float*)(smem + SM_BE) + c);
        bo2[nf] = *(const float2*)((const float*)(smem + SM_BOE) + c);
    }

    // ldmatrix lane addressing
    int aRow = m0 + (lane & 15);
    uint32_t aR0 = (uint32_t)(aRow * 256);
    uint32_t aR1 = (uint32_t)((aRow + 16) * 256);
    int aR7 = aRow & 7;
    int khA = lane >> 4;
    int bSel = ((lane >> 4) & 1) * 8 + (lane & 7);
    uint32_t bR0 = (uint32_t)((n0 + bSel) * 256);
    uint32_t bR1 = (uint32_t)((n0 + 16 + bSel) * 256);
    int bR7 = (n0 + bSel) & 7;
    int khB = (lane >> 3) & 1;

    int bufX = SM_T0, bufY = SM_T1;
    float acc[2][4][4];
    float* logit_s = (float*)(smem + SM_LOG);

    for (int jt = 0; jt < 8; ++jt) {
        int j0 = jt << 6;

        // prefetch next e-tile (stored into bufY after GEMM2)
        float4 pref[8];
        if (jt < 7) {
            const float4* esrc = (const float4*)(ebase + (size_t)(j0 + TJ) * H_);
#pragma unroll
            for (int l = 0; l < 8; ++l) pref[l] = esrc[tid + (l << 8)];
        }
        // prefetch K values for THIS tile's epilogue 1 (independent of GEMM1)
        float2 k0r[2][4], k1r[2][4];
#pragma unroll
        for (int mf = 0; mf < 2; ++mf)
#pragma unroll
            for (int nf = 0; nf < 4; ++nf) {
                int c = n0 + nf*8 + 2*t;
                int jl = m0 + mf*16 + g;
                k0r[mf][nf] = *(const float2*)(Kb + (size_t)(j0 + jl)*H_ + c);
                k1r[mf][nf] = *(const float2*)(Kb + (size_t)(j0 + jl + 8)*H_ + c);
            }

        // ---- GEMM1: Ee = e @ We ----
#pragma unroll
        for (int mf = 0; mf < 2; ++mf)
#pragma unroll
            for (int nf = 0; nf < 4; ++nf)
#pragma unroll
                for (int q = 0; q < 4; ++q) acc[mf][nf][q] = 0.f;
        gemm_tile(sb, bufX, SM_W, aR0, aR1, aR7, khA, bR0, bR1, bR7, khB, acc);
        __syncthreads();

        // ---- epilogue 1: inter = (Ee+be)*K*Q ; logits ; store inter fp16 ----
        {
            float psum[2][2][2] = {};
#pragma unroll
            for (int mf = 0; mf < 2; ++mf)
#pragma unroll
                for (int nf = 0; nf < 4; ++nf) {
                    int c = n0 + nf*8 + 2*t;
                    int jl = m0 + mf*16 + g;
                    float v0 = (acc[mf][nf][0] + be2[nf].x) * k0r[mf][nf].x * q2[nf].x;
                    float v1 = (acc[mf][nf][1] + be2[nf].y) * k0r[mf][nf].y * q2[nf].y;
                    float v2 = (acc[mf][nf][2] + be2[nf].x) * k1r[mf][nf].x * q2[nf].x;
                    float v3 = (acc[mf][nf][3] + be2[nf].y) * k1r[mf][nf].y * q2[nf].y;
                    psum[mf][0][nf >> 1] += v0 + v1;
                    psum[mf][1][nf >> 1] += v2 + v3;
                    int sw = (((c >> 3) ^ g) << 4) + 4*t;
                    *(uint32_t*)(smem + bufX + jl*256 + sw) =
                        pk2h(__float2half(v0), __float2half(v1));
                    *(uint32_t*)(smem + bufX + (jl + 8)*256 + sw) =
                        pk2h(__float2half(v2), __float2half(v3));
                }
#pragma unroll
            for (int mf = 0; mf < 2; ++mf)
#pragma unroll
                for (int half = 0; half < 2; ++half)
#pragma unroll
                    for (int hl = 0; hl < 2; ++hl) {
                        float s = psum[mf][half][hl];
                        s += __shfl_xor_sync(0xffffffffu, s, 1);
                        s += __shfl_xor_sync(0xffffffffu, s, 2);
                        if (t == 0) {
                            int j = m0 + mf*16 + g + half*8;
                            logit_s[(2*ni + hl)*N_ + j0 + j] = s;
                        }
                    }
        }
        __syncthreads();

        // ---- GEMM2: e_out = inter @ Woe ----
#pragma unroll
        for (int mf = 0; mf < 2; ++mf)
#pragma unroll
            for (int nf = 0; nf < 4; ++nf)
#pragma unroll
                for (int q = 0; q < 4; ++q) acc[mf][nf][q] = 0.f;
        gemm_tile(sb, bufX, SM_W + WPARTH, aR0, aR1, aR7, khA, bR0, bR1, bR7, khB, acc);
        __syncthreads();

        if (jt < 7) store_tile(smem, bufY, pref, tid);

        // ---- epilogue 2: e_out writes ----
#pragma unroll
        for (int mf = 0; mf < 2; ++mf)
#pragma unroll
            for (int nf = 0; nf < 4; ++nf) {
                int c = n0 + nf*8 + 2*t;
                int jl = m0 + mf*16 + g;
                size_t rb = OFF_EOUT + (((size_t)(b*N_ + i))*N_ + j0 + jl)*H_ + c;
                *(float2*)(out + rb) =
                    make_float2(acc[mf][nf][0] + bo2[nf].x, acc[mf][nf][1] + bo2[nf].y);
                *(float2*)(out + rb + 8*H_) =
                    make_float2(acc[mf][nf][2] + bo2[nf].x, acc[mf][nf][3] + bo2[nf].y);
            }
        __syncthreads();

        int tmp = bufX; bufX = bufY; bufY = tmp;
    }

    // ---- fused mask + softmax: warp w handles head w ----
    {
        const float* lg = logit_s + wid * N_;
        const float* mrow = mask + ((size_t)b*N_ + i)*N_;
        float4 vv[4];
        float mx = -3.4e38f;
#pragma unroll
        for (int c4 = 0; c4 < 4; ++c4) {
            int j = c4*128 + lane*4;
            float4 lv = *(const float4*)(lg + j);
            float4 mv = *(const float4*)(mrow + j);
            float4 v = make_float4(lv.x + mv.x, lv.y + mv.y, lv.z + mv.z, lv.w + mv.w);
            vv[c4] = v;
            mx = fmaxf(mx, fmaxf(fmaxf(v.x, v.y), fmaxf(v.z, v.w)));
        }
#pragma unroll
        for (int o = 16; o > 0; o >>= 1)
            mx = fmaxf(mx, __shfl_xor_sync(0xffffffffu, mx, o));
        float sum = 0.f;
#pragma unroll
        for (int c4 = 0; c4 < 4; ++c4) {
            vv[c4].x = expf(vv[c4].x - mx);
            vv[c4].y = expf(vv[c4].y - mx);
            vv[c4].z = expf(vv[c4].z - mx);
            vv[c4].w = expf(vv[c4].w - mx);
            sum += vv[c4].x + vv[c4].y + vv[c4].z + vv[c4].w;
        }
#pragma unroll
        for (int o = 16; o > 0; o >>= 1)
            sum += __shfl_xor_sync(0xffffffffu, sum, o);
        float inv = 1.f / sum;
        float* orow = out + OFF_SCORES + (((size_t)(b*NH_ + wid)*N_ + i) << 9);
#pragma unroll
        for (int c4 = 0; c4 < 4; ++c4) {
            int j = c4*128 + lane*4;
            *(float4*)(orow + j) = make_float4(vv[c4].x*inv, vv[c4].y*inv,
                                               vv[c4].z*inv, vv[c4].w*inv);
        }
    }
}

// ---------------------------------------------------------------------------
// out: att = scores @ V(=K) ; x_out = att @ Woh + boh.
// 4 i-rows per block; each thread loads K once, FMAs for all 4 i rows.
// ---------------------------------------------------------------------------
__global__ __launch_bounds__(512)
void out_kernel(const float* __restrict__ Woh, const float* __restrict__ boh,
                float* __restrict__ out) {
    extern __shared__ char osm[];
    float* sc    = (float*)osm;                    // [4][NH][N] = 64KB
    float* red   = (float*)(osm + 65536);          // [4][512]   = 8KB
    float* att_s = (float*)(osm + 65536 + 8192);   // [4][128]   = 2KB
    int blk = blockIdx.x;
    int b = blk >> 7, i0 = (blk & 127) << 2;
    int tid = threadIdx.x;

    const float* sp = out + OFF_SCORES;
    for (int u = tid; u < 4*NH_*N_; u += 512) {
        int il = u >> 12, h = (u >> 9) & 7, j = u & 511;
        sc[u] = sp[(((size_t)(b*NH_ + h)*N_ + i0 + il) << 9) + j];
    }
    __syncthreads();

    int c = tid & 127, t2 = tid >> 7;              // t2: j quarter (0..3)
    int h = c >> 4;
    const float* kp = g_K + (((size_t)b*N_) + t2*128)*H_ + c;
    const float* s0 = sc + 0*NH_*N_ + h*N_ + t2*128;
    const float* s1 = sc + 1*NH_*N_ + h*N_ + t2*128;
    const float* s2 = sc + 2*NH_*N_ + h*N_ + t2*128;
    const float* s3 = sc + 3*NH_*N_ + h*N_ + t2*128;
    float a0 = 0.f, a1 = 0.f, a2 = 0.f, a3 = 0.f;
#pragma unroll 8
    for (int j = 0; j < 128; ++j) {
        float kv = kp[(size_t)j*H_];
        a0 = fmaf(s0[j], kv, a0);
        a1 = fmaf(s1[j], kv, a1);
        a2 = fmaf(s2[j], kv, a2);
        a3 = fmaf(s3[j], kv, a3);
    }
    red[0*512 + tid] = a0;
    red[1*512 + tid] = a1;
    red[2*512 + tid] = a2;
    red[3*512 + tid] = a3;
    __syncthreads();
    {
        int il = tid >> 7, cc = tid & 127;         // 512 threads = 4 il x 128 c
        att_s[il*H_ + cc] = red[il*512 + cc] + red[il*512 + 128 + cc] +
                            red[il*512 + 256 + cc] + red[il*512 + 384 + cc];
    }
    __syncthreads();
    {
        int il = tid >> 7, cc = tid & 127;
        float o = boh[cc];
        const float* as = att_s + il*H_;
#pragma unroll 8
        for (int k = 0; k < H_; ++k)
            o = fmaf(as[k], Woh[k*H_ + cc], o);
        out[((size_t)(b*N_) + i0 + il)*H_ + cc] = o;
    }
}
#define OUT_SMEM (65536 + 8192 + 2048)

// ---------------------------------------------------------------------------
extern "C" void kernel_launch(void* const* d_in, const int* in_sizes, int n_in,
                              void* d_out, int out_size) {
    const float* x    = (const float*)d_in[0];
    const float* e    = (const float*)d_in[1];
    const float* mask = (const float*)d_in[2];
    const float* Wq   = (const float*)d_in[3];
    const float* bq   = (const float*)d_in[4];
    const float* Wk   = (const float*)d_in[5];
    const float* bk   = (const float*)d_in[6];
    const float* We   = (const float*)d_in[7];
    const float* be   = (const float*)d_in[8];
    const float* Woh  = (const float*)d_in[9];
    const float* boh  = (const float*)d_in[10];
    const float* Woe  = (const float*)d_in[11];
    const float* boe  = (const float*)d_in[12];
    float* out = (float*)d_out;

    cudaFuncSetAttribute(edge_kernel, cudaFuncAttributeMaxDynamicSharedMemorySize, SM_TOTAL);
    cudaFuncSetAttribute(out_kernel, cudaFuncAttributeMaxDynamicSharedMemorySize, OUT_SMEM);

    prepqk_kernel<<<64 + B_*N_/2, 256>>>(We, Woe, be, boe, x, Wq, bq, Wk, bk);
    edge_kernel<<<B_*N_, 256, SM_TOTAL>>>(e, mask, out);
    out_kernel<<<B_*N_/4, 512, OUT_SMEM>>>(Woh, boh, out);
}

// round 14
// speedup vs baseline: 1.0222x; 1.0068x over previous
#include <cuda_runtime.h>
#include <cuda_fp16.h>
#include <cstdint>
#include <math.h>

#define B_   2
#define N_   512
#define H_   128
#define NH_  8
#define TJ   64

#define OFF_EOUT   ((size_t)(B_*N_*H_))
#define OFF_SCORES (OFF_EOUT + (size_t)B_*N_*N_*H_)

// ---- smem layout (bytes): single e-tile buffer + separate inter buffer ----
#define SM_W    0               // We fp16 (32KB) | Woe fp16 (32KB)
#define WPARTH  32768
#define SM_T    65536           // e-tile buffer 16KB fp16
#define SM_I    81920           // inter buffer 16KB fp16
#define SM_LOG  98304           // logits [8][512] f32 = 16KB
#define SM_Q    114688
#define SM_BE   115200
#define SM_BOE  115712
#define SM_TOTAL 116224

__device__ float g_Q[B_*N_*H_];   // (x@Wq+bq)*0.25
__device__ float g_K[B_*N_*H_];   // x@Wk+bk (= V)
__device__ float g_be[H_];
__device__ float g_boe[H_];
__device__ __align__(16) unsigned char g_Wimg[2*WPARTH];

static __device__ __forceinline__ uint32_t smem_u32(const void* p) {
    uint32_t a;
    asm("{ .reg .u64 t; cvta.to.shared.u64 t, %1; cvt.u32.u64 %0, t; }" : "=r"(a) : "l"(p));
    return a;
}
static __device__ __forceinline__ uint32_t pk2h(__half a, __half b) {
    __half2 t = __halves2half2(a, b);
    return *(uint32_t*)&t;
}
static __device__ __forceinline__ void mma16816(float* c,
        uint32_t a0, uint32_t a1, uint32_t a2, uint32_t a3,
        uint32_t b0, uint32_t b1) {
    asm volatile(
        "mma.sync.aligned.m16n8k16.row.col.f32.f16.f16.f32 "
        "{%0,%1,%2,%3},{%4,%5,%6,%7},{%8,%9},{%0,%1,%2,%3};"
        : "+f"(c[0]), "+f"(c[1]), "+f"(c[2]), "+f"(c[3])
        : "r"(a0), "r"(a1), "r"(a2), "r"(a3), "r"(b0), "r"(b1));
}
#define LDSM4(r, addr) \
    asm volatile("ldmatrix.sync.aligned.m8n8.x4.shared.b16 {%0,%1,%2,%3}, [%4];" \
        : "=r"((r)[0]), "=r"((r)[1]), "=r"((r)[2]), "=r"((r)[3]) : "r"(addr))

// phys byte offset within a tile: row*256 + ((k/8 ^ (row&7))*16) + (k&7)*2
static __device__ __host__ __forceinline__ int tswz(int row, int k) {
    return row*256 + ((((k>>3) ^ (row&7)))<<4) + (k&7)*2;
}

// ---------------------------------------------------------------------------
// prep + qk fused: blocks 0..63 build weight image; blocks 64.. do Q/K rows
// ---------------------------------------------------------------------------
__global__ void prepqk_kernel(const float* __restrict__ We, const float* __restrict__ Woe,
                              const float* __restrict__ be, const float* __restrict__ boe,
                              const float* __restrict__ x,
                              const float* __restrict__ Wq, const float* __restrict__ bq,
                              const float* __restrict__ Wk, const float* __restrict__ bk) {
    if (blockIdx.x < 64) {
        int idx = blockIdx.x * 256 + threadIdx.x;   // 16384
        int c = idx >> 7, k = idx & 127;
        int byt = tswz(c, k);
        *(__half*)(g_Wimg + byt)          = __float2half(We[k*H_ + c]);
        *(__half*)(g_Wimg + WPARTH + byt) = __float2half(Woe[k*H_ + c]);
        if (idx < H_) { g_be[idx] = be[idx]; g_boe[idx] = boe[idx]; }
        return;
    }
    // Q/K: 2 rows per block (256 threads)
    __shared__ float xs[2][H_];
    int row0 = (blockIdx.x - 64) * 2;
    int rl = threadIdx.x >> 7, c = threadIdx.x & 127;
    int row = row0 + rl;
    xs[rl][c] = x[row*H_ + c];
    __syncthreads();
    float aq = bq[c], ak = bk[c];
#pragma unroll 8
    for (int k = 0; k < H_; ++k) {
        float xv = xs[rl][k];
        aq = fmaf(xv, Wq[k*H_ + c], aq);
        ak = fmaf(xv, Wk[k*H_ + c], ak);
    }
    g_Q[row*H_ + c] = 0.25f * aq;
    g_K[row*H_ + c] = ak;
}

// ---------------------------------------------------------------------------
// edge helpers
// ---------------------------------------------------------------------------
static __device__ __forceinline__ void store_tile(char* smem, int buf,
        const float4* pref, int tid) {
#pragma unroll
    for (int l = 0; l < 8; ++l) {
        int u = tid + (l << 8);
        int j = u >> 5, kq = u & 31;
        int k4 = kq << 2;
        int base = buf + tswz(j, k4);
        float4 v = pref[l];
        *(uint2*)(smem + base) = make_uint2(
            pk2h(__float2half(v.x), __float2half(v.y)),
            pk2h(__float2half(v.z), __float2half(v.w)));
    }
}

// C[64x128] += A[64x128] @ B[128x128]^T, fp16 single pass, ldmatrix loads
static __device__ __forceinline__ void gemm_tile(uint32_t sb, uint32_t aB, uint32_t bB,
        uint32_t aR0, uint32_t aR1, int aR7, int khA,
        uint32_t bR0, uint32_t bR1, int bR7, int khB,
        float (&acc)[2][4][4]) {
#pragma unroll
    for (int ks = 0; ks < 8; ++ks) {
        uint32_t swA = (uint32_t)((((ks << 1) | khA) ^ aR7) << 4);
        uint32_t swB = (uint32_t)((((ks << 1) | khB) ^ bR7) << 4);
        uint32_t a0[4], a1[4], b0[4], b1[4];
        LDSM4(a0, sb + aB + aR0 + swA);
        LDSM4(a1, sb + aB + aR1 + swA);
        LDSM4(b0, sb + bB + bR0 + swB);
        LDSM4(b1, sb + bB + bR1 + swB);
        mma16816(acc[0][0], a0[0],a0[1],a0[2],a0[3], b0[0], b0[1]);
        mma16816(acc[0][1], a0[0],a0[1],a0[2],a0[3], b0[2], b0[3]);
        mma16816(acc[0][2], a0[0],a0[1],a0[2],a0[3], b1[0], b1[1]);
        mma16816(acc[0][3], a0[0],a0[1],a0[2],a0[3], b1[2], b1[3]);
        mma16816(acc[1][0], a1[0],a1[1],a1[2],a1[3], b0[0], b0[1]);
        mma16816(acc[1][1], a1[0],a1[1],a1[2],a1[3], b0[2], b0[3]);
        mma16816(acc[1][2], a1[0],a1[1],a1[2],a1[3], b1[0], b1[1]);
        mma16816(acc[1][3], a1[0],a1[1],a1[2],a1[3], b1[2], b1[3]);
    }
}

// ---------------------------------------------------------------------------
// edge: GEMM1 -> epi1 (no barrier between: register dataflow, inter goes to
// SM_I so it never aliases the e-tile GEMM1 is reading) -> B1 -> GEMM2 +
// store_tile(next) + epi2 -> B2. 2 barriers/tile instead of 4.
// ---------------------------------------------------------------------------
__global__ __launch_bounds__(256, 1)
void edge_kernel(const float* __restrict__ e, const float* __restrict__ mask,
                 float* __restrict__ out) {
    extern __shared__ char smem[];
    uint32_t sb = smem_u32(smem);
    int tid = threadIdx.x, wid = tid >> 5, lane = tid & 31;
    int g = lane >> 2, t = lane & 3;
    int mi = wid & 1, ni = wid >> 1;
    int m0 = mi * 32, n0 = ni * 32;
    int row = blockIdx.x, b = row >> 9, i = row & 511;

    {
        const float4* w4 = (const float4*)g_Wimg;
        float4* d4 = (float4*)smem;
#pragma unroll
        for (int u = tid; u < 4096; u += 256) d4[u] = w4[u];
    }
    if (tid < H_) {
        ((float*)(smem + SM_Q))[tid]   = g_Q[(b*N_ + i)*H_ + tid];
        ((float*)(smem + SM_BE))[tid]  = g_be[tid];
        ((float*)(smem + SM_BOE))[tid] = g_boe[tid];
    }

    const float* Kb = g_K + (size_t)b * N_ * H_;
    const float* ebase = e + ((size_t)(b*N_ + i)) * N_ * H_;

    {
        float4 pref[8];
        const float4* esrc = (const float4*)ebase;
#pragma unroll
        for (int l = 0; l < 8; ++l) pref[l] = esrc[tid + (l << 8)];
        store_tile(smem, SM_T, pref, tid);
    }
    __syncthreads();

    float2 q2[4], be2[4], bo2[4];
#pragma unroll
    for (int nf = 0; nf < 4; ++nf) {
        int c = n0 + nf*8 + 2*t;
        q2[nf]  = *(const float2*)((const float*)(smem + SM_Q)  + c);
        be2[nf] = *(const float2*)((const float*)(smem + SM_BE) + c);
        bo2[nf] = *(const float2*)((const float*)(smem + SM_BOE) + c);
    }

    // ldmatrix lane addressing
    int aRow = m0 + (lane & 15);
    uint32_t aR0 = (uint32_t)(aRow * 256);
    uint32_t aR1 = (uint32_t)((aRow + 16) * 256);
    int aR7 = aRow & 7;
    int khA = lane >> 4;
    int bSel = ((lane >> 4) & 1) * 8 + (lane & 7);
    uint32_t bR0 = (uint32_t)((n0 + bSel) * 256);
    uint32_t bR1 = (uint32_t)((n0 + 16 + bSel) * 256);
    int bR7 = (n0 + bSel) & 7;
    int khB = (lane >> 3) & 1;

    float acc[2][4][4];
    float* logit_s = (float*)(smem + SM_LOG);

    for (int jt = 0; jt < 8; ++jt) {
        int j0 = jt << 6;

        // prefetch next e-tile (stored into SM_T after B1)
        float4 pref[8];
        if (jt < 7) {
            const float4* esrc = (const float4*)(ebase + (size_t)(j0 + TJ) * H_);
#pragma unroll
            for (int l = 0; l < 8; ++l) pref[l] = esrc[tid + (l << 8)];
        }
        // prefetch K values for this tile's epi1 (independent of GEMM1)
        float2 k0r[2][4], k1r[2][4];
#pragma unroll
        for (int mf = 0; mf < 2; ++mf)
#pragma unroll
            for (int nf = 0; nf < 4; ++nf) {
                int c = n0 + nf*8 + 2*t;
                int jl = m0 + mf*16 + g;
                k0r[mf][nf] = *(const float2*)(Kb + (size_t)(j0 + jl)*H_ + c);
                k1r[mf][nf] = *(const float2*)(Kb + (size_t)(j0 + jl + 8)*H_ + c);
            }

        // ---- GEMM1: Ee = e @ We  (reads SM_T) ----
#pragma unroll
        for (int mf = 0; mf < 2; ++mf)
#pragma unroll
            for (int nf = 0; nf < 4; ++nf)
#pragma unroll
                for (int q = 0; q < 4; ++q) acc[mf][nf][q] = 0.f;
        gemm_tile(sb, SM_T, SM_W, aR0, aR1, aR7, khA, bR0, bR1, bR7, khB, acc);

        // ---- epi1 (NO barrier: uses own regs; writes SM_I, not SM_T) ----
        {
            float psum[2][2][2] = {};
#pragma unroll
            for (int mf = 0; mf < 2; ++mf)
#pragma unroll
                for (int nf = 0; nf < 4; ++nf) {
                    int c = n0 + nf*8 + 2*t;
                    int jl = m0 + mf*16 + g;
                    float v0 = (acc[mf][nf][0] + be2[nf].x) * k0r[mf][nf].x * q2[nf].x;
                    float v1 = (acc[mf][nf][1] + be2[nf].y) * k0r[mf][nf].y * q2[nf].y;
                    float v2 = (acc[mf][nf][2] + be2[nf].x) * k1r[mf][nf].x * q2[nf].x;
                    float v3 = (acc[mf][nf][3] + be2[nf].y) * k1r[mf][nf].y * q2[nf].y;
                    psum[mf][0][nf >> 1] += v0 + v1;
                    psum[mf][1][nf >> 1] += v2 + v3;
                    int sw = (((c >> 3) ^ g) << 4) + 4*t;
                    *(uint32_t*)(smem + SM_I + jl*256 + sw) =
                        pk2h(__float2half(v0), __float2half(v1));
                    *(uint32_t*)(smem + SM_I + (jl + 8)*256 + sw) =
                        pk2h(__float2half(v2), __float2half(v3));
                }
#pragma unroll
            for (int mf = 0; mf < 2; ++mf)
#pragma unroll
                for (int half = 0; half < 2; ++half)
#pragma unroll
                    for (int hl = 0; hl < 2; ++hl) {
                        float s = psum[mf][half][hl];
                        s += __shfl_xor_sync(0xffffffffu, s, 1);
                        s += __shfl_xor_sync(0xffffffffu, s, 2);
                        if (t == 0) {
                            int j = m0 + mf*16 + g + half*8;
                            logit_s[(2*ni + hl)*N_ + j0 + j] = s;
                        }
                    }
        }
        __syncthreads();   // B1: SM_I complete; SM_T free for next tile

        // ---- GEMM2 (reads SM_I) + store next tile (writes SM_T) ----
#pragma unroll
        for (int mf = 0; mf < 2; ++mf)
#pragma unroll
            for (int nf = 0; nf < 4; ++nf)
#pragma unroll
                for (int q = 0; q < 4; ++q) acc[mf][nf][q] = 0.f;
        gemm_tile(sb, SM_I, SM_W + WPARTH, aR0, aR1, aR7, khA, bR0, bR1, bR7, khB, acc);

        if (jt < 7) store_tile(smem, SM_T, pref, tid);

        // ---- epi2: e_out writes (registers only) ----
#pragma unroll
        for (int mf = 0; mf < 2; ++mf)
#pragma unroll
            for (int nf = 0; nf < 4; ++nf) {
                int c = n0 + nf*8 + 2*t;
                int jl = m0 + mf*16 + g;
                size_t rb = OFF_EOUT + (((size_t)(b*N_ + i))*N_ + j0 + jl)*H_ + c;
                *(float2*)(out + rb) =
                    make_float2(acc[mf][nf][0] + bo2[nf].x, acc[mf][nf][1] + bo2[nf].y);
                *(float2*)(out + rb + 8*H_) =
                    make_float2(acc[mf][nf][2] + bo2[nf].x, acc[mf][nf][3] + bo2[nf].y);
            }
        __syncthreads();   // B2: SM_T written; SM_I free for next epi1
    }

    // ---- fused mask + softmax: warp w handles head w ----
    {
        const float* lg = logit_s + wid * N_;
        const float* mrow = mask + ((size_t)b*N_ + i)*N_;
        float4 vv[4];
        float mx = -3.4e38f;
#pragma unroll
        for (int c4 = 0; c4 < 4; ++c4) {
            int j = c4*128 + lane*4;
            float4 lv = *(const float4*)(lg + j);
            float4 mv = *(const float4*)(mrow + j);
            float4 v = make_float4(lv.x + mv.x, lv.y + mv.y, lv.z + mv.z, lv.w + mv.w);
            vv[c4] = v;
            mx = fmaxf(mx, fmaxf(fmaxf(v.x, v.y), fmaxf(v.z, v.w)));
        }
#pragma unroll
        for (int o = 16; o > 0; o >>= 1)
            mx = fmaxf(mx, __shfl_xor_sync(0xffffffffu, mx, o));
        float sum = 0.f;
#pragma unroll
        for (int c4 = 0; c4 < 4; ++c4) {
            vv[c4].x = expf(vv[c4].x - mx);
            vv[c4].y = expf(vv[c4].y - mx);
            vv[c4].z = expf(vv[c4].z - mx);
            vv[c4].w = expf(vv[c4].w - mx);
            sum += vv[c4].x + vv[c4].y + vv[c4].z + vv[c4].w;
        }
#pragma unroll
        for (int o = 16; o > 0; o >>= 1)
            sum += __shfl_xor_sync(0xffffffffu, sum, o);
        float inv = 1.f / sum;
        float* orow = out + OFF_SCORES + (((size_t)(b*NH_ + wid)*N_ + i) << 9);
#pragma unroll
        for (int c4 = 0; c4 < 4; ++c4) {
            int j = c4*128 + lane*4;
            *(float4*)(orow + j) = make_float4(vv[c4].x*inv, vv[c4].y*inv,
                                               vv[c4].z*inv, vv[c4].w*inv);
        }
    }
}

// ---------------------------------------------------------------------------
// out: att = scores @ V(=K) ; x_out = att @ Woh + boh.
// 2 i-rows per block (r9-measured variant).
// ---------------------------------------------------------------------------
__global__ __launch_bounds__(512)
void out_kernel(const float* __restrict__ Woh, const float* __restrict__ boh,
                float* __restrict__ out) {
    __shared__ float sc[2*NH_*N_];   // 32 KB
    __shared__ float red[2][512];
    __shared__ float att_s[2][H_];
    int blk = blockIdx.x;
    int b = blk >> 8, i0 = (blk & 255) << 1;
    int tid = threadIdx.x;

    const float* sp = out + OFF_SCORES;
    for (int u = tid; u < 2*NH_*N_; u += 512) {
        int il = u >> 12, h = (u >> 9) & 7, j = u & 511;
        sc[u] = sp[(((size_t)(b*NH_ + h)*N_ + i0 + il) << 9) + j];
    }
    __syncthreads();

    int c = tid & 127, t2 = tid >> 7;
    int h = c >> 4;
    const float* kp = g_K + (((size_t)b*N_) + t2*128)*H_ + c;
    const float* s0 = sc + h*N_ + t2*128;
    const float* s1 = sc + NH_*N_ + h*N_ + t2*128;
    float a0 = 0.f, a1 = 0.f;
#pragma unroll 8
    for (int j = 0; j < 128; ++j) {
        float kv = kp[(size_t)j*H_];
        a0 = fmaf(s0[j], kv, a0);
        a1 = fmaf(s1[j], kv, a1);
    }
    red[0][tid] = a0;
    red[1][tid] = a1;
    __syncthreads();
    if (tid < 256) {
        int il = tid >> 7, cc = tid & 127;
        att_s[il][cc] = red[il][cc] + red[il][128 + cc] +
                        red[il][256 + cc] + red[il][384 + cc];
    }
    __syncthreads();
    if (tid < 256) {
        int il = tid >> 7, cc = tid & 127;
        float o = boh[cc];
#pragma unroll 8
        for (int k = 0; k < H_; ++k)
            o = fmaf(att_s[il][k], Woh[k*H_ + cc], o);
        out[((size_t)(b*N_) + i0 + il)*H_ + cc] = o;
    }
}

// ---------------------------------------------------------------------------
extern "C" void kernel_launch(void* const* d_in, const int* in_sizes, int n_in,
                              void* d_out, int out_size) {
    const float* x    = (const float*)d_in[0];
    const float* e    = (const float*)d_in[1];
    const float* mask = (const float*)d_in[2];
    const float* Wq   = (const float*)d_in[3];
    const float* bq   = (const float*)d_in[4];
    const float* Wk   = (const float*)d_in[5];
    const float* bk   = (const float*)d_in[6];
    const float* We   = (const float*)d_in[7];
    const float* be   = (const float*)d_in[8];
    const float* Woh  = (const float*)d_in[9];
    const float* boh  = (const float*)d_in[10];
    const float* Woe  = (const float*)d_in[11];
    const float* boe  = (const float*)d_in[12];
    float* out = (float*)d_out;

    cudaFuncSetAttribute(edge_kernel, cudaFuncAttributeMaxDynamicSharedMemorySize, SM_TOTAL);

    prepqk_kernel<<<64 + B_*N_/2, 256>>>(We, Woe, be, boe, x, Wq, bq, Wk, bk);
    edge_kernel<<<B_*N_, 256, SM_TOTAL>>>(e, mask, out);
    out_kernel<<<B_*N_/2, 512>>>(Woh, boh, out);
}

// round 16
// speedup vs baseline: 1.1608x; 1.1356x over previous
#include <cuda_runtime.h>
#include <cuda_fp16.h>
#include <cstdint>
#include <math.h>

#define B_   2
#define N_   512
#define H_   128
#define NH_  8
#define TJ   64
#define NROW (B_*N_)

#define OFF_EOUT   ((size_t)(B_*N_*H_))
#define OFF_SCORES (OFF_EOUT + (size_t)B_*N_*N_*H_)

// ---- smem layout (bytes): e-tile + separate inter buffer (r14 structure) ----
#define SM_W    0               // We fp16 (32KB) | Woe fp16 (32KB)
#define WPARTH  32768
#define SM_T    65536           // e-tile buffer 16KB fp16
#define SM_I    81920           // inter buffer 16KB fp16
#define SM_LOG  98304           // logits [8][512] f32 = 16KB
#define SM_TOTAL 114688

__device__ float g_Q[NROW*H_];    // (x@Wq+bq)*0.25
__device__ float g_K[NROW*H_];    // x@Wk+bk (= V)
__device__ float g_be[H_];
__device__ float g_boe[H_];
__device__ __align__(16) unsigned char g_Wimg[2*WPARTH];

static __device__ __forceinline__ uint32_t smem_u32(const void* p) {
    uint32_t a;
    asm("{ .reg .u64 t; cvta.to.shared.u64 t, %1; cvt.u32.u64 %0, t; }" : "=r"(a) : "l"(p));
    return a;
}
static __device__ __forceinline__ uint32_t pk2h(__half a, __half b) {
    __half2 t = __halves2half2(a, b);
    return *(uint32_t*)&t;
}
static __device__ __forceinline__ void mma16816(float* c,
        uint32_t a0, uint32_t a1, uint32_t a2, uint32_t a3,
        uint32_t b0, uint32_t b1) {
    asm volatile(
        "mma.sync.aligned.m16n8k16.row.col.f32.f16.f16.f32 "
        "{%0,%1,%2,%3},{%4,%5,%6,%7},{%8,%9},{%0,%1,%2,%3};"
        : "+f"(c[0]), "+f"(c[1]), "+f"(c[2]), "+f"(c[3])
        : "r"(a0), "r"(a1), "r"(a2), "r"(a3), "r"(b0), "r"(b1));
}
#define LDSM4(r, addr) \
    asm volatile("ldmatrix.sync.aligned.m8n8.x4.shared.b16 {%0,%1,%2,%3}, [%4];" \
        : "=r"((r)[0]), "=r"((r)[1]), "=r"((r)[2]), "=r"((r)[3]) : "r"(addr))

// phys byte offset within a tile: row*256 + ((k/8 ^ (row&7))*16) + (k&7)*2
static __device__ __host__ __forceinline__ int tswz(int row, int k) {
    return row*256 + ((((k>>3) ^ (row&7)))<<4) + (k&7)*2;
}

// ---------------------------------------------------------------------------
// prep + qk fused: blocks 0..63 build weight image; blocks 64.. one row each
// with 2-way split-k (halves the serial FMA/LDG chain).
// ---------------------------------------------------------------------------
__global__ void prepqk_kernel(const float* __restrict__ We, const float* __restrict__ Woe,
                              const float* __restrict__ be, const float* __restrict__ boe,
                              const float* __restrict__ x,
                              const float* __restrict__ Wq, const float* __restrict__ bq,
                              const float* __restrict__ Wk, const float* __restrict__ bk) {
    if (blockIdx.x < 64) {
        int idx = blockIdx.x * 256 + threadIdx.x;   // 16384
        int c = idx >> 7, k = idx & 127;
        int byt = tswz(c, k);
        *(__half*)(g_Wimg + byt)          = __float2half(We[k*H_ + c]);
        *(__half*)(g_Wimg + WPARTH + byt) = __float2half(Woe[k*H_ + c]);
        if (idx < H_) { g_be[idx] = be[idx]; g_boe[idx] = boe[idx]; }
        return;
    }
    int row = blockIdx.x - 64;              // 0..1023
    __shared__ float xs[H_];
    __shared__ float redq[256], redk[256];
    int tid = threadIdx.x;
    if (tid < H_) xs[tid] = x[row*H_ + tid];
    __syncthreads();
    int c = tid & 127, kh = tid >> 7;       // split-k half
    int kb = kh * 64;
    float aq = 0.f, ak = 0.f;
#pragma unroll 16
    for (int k = 0; k < 64; ++k) {
        float xv = xs[kb + k];
        aq = fmaf(xv, Wq[(kb + k)*H_ + c], aq);
        ak = fmaf(xv, Wk[(kb + k)*H_ + c], ak);
    }
    redq[tid] = aq;
    redk[tid] = ak;
    __syncthreads();
    if (tid < H_) {
        g_Q[row*H_ + tid] = 0.25f * (redq[tid] + redq[tid + 128] + bq[tid]);
        g_K[row*H_ + tid] = redk[tid] + redk[tid + 128] + bk[tid];
    }
}

// ---------------------------------------------------------------------------
// edge helpers
// ---------------------------------------------------------------------------
static __device__ __forceinline__ void store_tile(char* smem, int buf,
        const float4* pref, int tid) {
#pragma unroll
    for (int l = 0; l < 8; ++l) {
        int u = tid + (l << 8);
        int j = u >> 5, kq = u & 31;
        int k4 = kq << 2;
        int base = buf + tswz(j, k4);
        float4 v = pref[l];
        *(uint2*)(smem + base) = make_uint2(
            pk2h(__float2half(v.x), __float2half(v.y)),
            pk2h(__float2half(v.z), __float2half(v.w)));
    }
}

// C[64x128] += A[64x128] @ B[128x128]^T, fp16 single pass, ldmatrix loads
static __device__ __forceinline__ void gemm_tile(uint32_t sb, uint32_t aB, uint32_t bB,
        uint32_t aR0, uint32_t aR1, int aR7, int khA,
        uint32_t bR0, uint32_t bR1, int bR7, int khB,
        float (&acc)[2][4][4]) {
#pragma unroll
    for (int ks = 0; ks < 8; ++ks) {
        uint32_t swA = (uint32_t)((((ks << 1) | khA) ^ aR7) << 4);
        uint32_t swB = (uint32_t)((((ks << 1) | khB) ^ bR7) << 4);
        uint32_t a0[4], a1[4], b0[4], b1[4];
        LDSM4(a0, sb + aB + aR0 + swA);
        LDSM4(a1, sb + aB + aR1 + swA);
        LDSM4(b0, sb + bB + bR0 + swB);
        LDSM4(b1, sb + bB + bR1 + swB);
        mma16816(acc[0][0], a0[0],a0[1],a0[2],a0[3], b0[0], b0[1]);
        mma16816(acc[0][1], a0[0],a0[1],a0[2],a0[3], b0[2], b0[3]);
        mma16816(acc[0][2], a0[0],a0[1],a0[2],a0[3], b1[0], b1[1]);
        mma16816(acc[0][3], a0[0],a0[1],a0[2],a0[3], b1[2], b1[3]);
        mma16816(acc[1][0], a1[0],a1[1],a1[2],a1[3], b0[0], b0[1]);
        mma16816(acc[1][1], a1[0],a1[1],a1[2],a1[3], b0[2], b0[3]);
        mma16816(acc[1][2], a1[0],a1[1],a1[2],a1[3], b1[0], b1[1]);
        mma16816(acc[1][3], a1[0],a1[1],a1[2],a1[3], b1[2], b1[3]);
    }
}

// ---------------------------------------------------------------------------
// edge: PERSISTENT (grid=148). Weights staged once; row loop; next row's
// tile 0 prefetched during jt=7's GEMM2 so only the first row pays a
// prologue. Per tile: GEMM1 -> epi1 (no barrier, inter to SM_I) -> B1 ->
// GEMM2 + store next tile + epi2 -> B2.
// ---------------------------------------------------------------------------
__global__ __launch_bounds__(256, 1)
void edge_kernel(const float* __restrict__ e, const float* __restrict__ mask,
                 float* __restrict__ out) {
    extern __shared__ char smem[];
    uint32_t sb = smem_u32(smem);
    int tid = threadIdx.x, wid = tid >> 5, lane = tid & 31;
    int g = lane >> 2, t = lane & 3;
    int mi = wid & 1, ni = wid >> 1;
    int m0 = mi * 32, n0 = ni * 32;
    int grid = gridDim.x;

    // stage weights once
    {
        const float4* w4 = (const float4*)g_Wimg;
        float4* d4 = (float4*)smem;
#pragma unroll
        for (int u = tid; u < 4096; u += 256) d4[u] = w4[u];
    }

    // loop-invariant per-thread column constants
    float2 be2[4], bo2[4];
#pragma unroll
    for (int nf = 0; nf < 4; ++nf) {
        int c = n0 + nf*8 + 2*t;
        be2[nf] = *(const float2*)(g_be + c);
        bo2[nf] = *(const float2*)(g_boe + c);
    }

    // ldmatrix lane addressing
    int aRow = m0 + (lane & 15);
    uint32_t aR0 = (uint32_t)(aRow * 256);
    uint32_t aR1 = (uint32_t)((aRow + 16) * 256);
    int aR7 = aRow & 7;
    int khA = lane >> 4;
    int bSel = ((lane >> 4) & 1) * 8 + (lane & 7);
    uint32_t bR0 = (uint32_t)((n0 + bSel) * 256);
    uint32_t bR1 = (uint32_t)((n0 + 16 + bSel) * 256);
    int bR7 = (n0 + bSel) & 7;
    int khB = (lane >> 3) & 1;

    float acc[2][4][4];
    float* logit_s = (float*)(smem + SM_LOG);

    // prologue: stage tile 0 of first row
    {
        const float4* esrc = (const float4*)(e + (size_t)blockIdx.x * N_ * H_);
        float4 pref[8];
#pragma unroll
        for (int l = 0; l < 8; ++l) pref[l] = esrc[tid + (l << 8)];
        store_tile(smem, SM_T, pref, tid);
    }
    __syncthreads();

    for (int row = blockIdx.x; row < NROW; row += grid) {
        int b = row >> 9, i = row & 511;
        const float* Kb = g_K + (size_t)b * N_ * H_;
        const float* ebase = e + (size_t)row * N_ * H_;

        float2 q2[4];
#pragma unroll
        for (int nf = 0; nf < 4; ++nf)
            q2[nf] = *(const float2*)(g_Q + (size_t)row*H_ + n0 + nf*8 + 2*t);

        for (int jt = 0; jt < 8; ++jt) {
            int j0 = jt << 6;

            // prefetch: next tile of this row, or tile 0 of the next row
            float4 pref[8];
            bool havePref = true;
            if (jt < 7) {
                const float4* esrc = (const float4*)(ebase + (size_t)(j0 + TJ) * H_);
#pragma unroll
                for (int l = 0; l < 8; ++l) pref[l] = esrc[tid + (l << 8)];
            } else if (row + grid < NROW) {
                const float4* esrc = (const float4*)(e + (size_t)(row + grid) * N_ * H_);
#pragma unroll
                for (int l = 0; l < 8; ++l) pref[l] = esrc[tid + (l << 8)];
            } else havePref = false;

            // prefetch K values for this tile's epi1
            float2 k0r[2][4], k1r[2][4];
#pragma unroll
            for (int mf = 0; mf < 2; ++mf)
#pragma unroll
                for (int nf = 0; nf < 4; ++nf) {
                    int c = n0 + nf*8 + 2*t;
                    int jl = m0 + mf*16 + g;
                    k0r[mf][nf] = *(const float2*)(Kb + (size_t)(j0 + jl)*H_ + c);
                    k1r[mf][nf] = *(const float2*)(Kb + (size_t)(j0 + jl + 8)*H_ + c);
                }

            // ---- GEMM1: Ee = e @ We (reads SM_T) ----
#pragma unroll
            for (int mf = 0; mf < 2; ++mf)
#pragma unroll
                for (int nf = 0; nf < 4; ++nf)
#pragma unroll
                    for (int q = 0; q < 4; ++q) acc[mf][nf][q] = 0.f;
            gemm_tile(sb, SM_T, SM_W, aR0, aR1, aR7, khA, bR0, bR1, bR7, khB, acc);

            // ---- epi1: no barrier (own regs; writes SM_I) ----
            {
                float psum[2][2][2] = {};
#pragma unroll
                for (int mf = 0; mf < 2; ++mf)
#pragma unroll
                    for (int nf = 0; nf < 4; ++nf) {
                        int c = n0 + nf*8 + 2*t;
                        int jl = m0 + mf*16 + g;
                        float v0 = (acc[mf][nf][0] + be2[nf].x) * k0r[mf][nf].x * q2[nf].x;
                        float v1 = (acc[mf][nf][1] + be2[nf].y) * k0r[mf][nf].y * q2[nf].y;
                        float v2 = (acc[mf][nf][2] + be2[nf].x) * k1r[mf][nf].x * q2[nf].x;
                        float v3 = (acc[mf][nf][3] + be2[nf].y) * k1r[mf][nf].y * q2[nf].y;
                        psum[mf][0][nf >> 1] += v0 + v1;
                        psum[mf][1][nf >> 1] += v2 + v3;
                        int sw = (((c >> 3) ^ g) << 4) + 4*t;
                        *(uint32_t*)(smem + SM_I + jl*256 + sw) =
                            pk2h(__float2half(v0), __float2half(v1));
                        *(uint32_t*)(smem + SM_I + (jl + 8)*256 + sw) =
                            pk2h(__float2half(v2), __float2half(v3));
                    }
#pragma unroll
                for (int mf = 0; mf < 2; ++mf)
#pragma unroll
                    for (int half = 0; half < 2; ++half)
#pragma unroll
                        for (int hl = 0; hl < 2; ++hl) {
                            float s = psum[mf][half][hl];
                            s += __shfl_xor_sync(0xffffffffu, s, 1);
                            s += __shfl_xor_sync(0xffffffffu, s, 2);
                            if (t == 0) {
                                int j = m0 + mf*16 + g + half*8;
                                logit_s[(2*ni + hl)*N_ + j0 + j] = s;
                            }
                        }
            }
            __syncthreads();   // B1: SM_I complete; SM_T free

            // ---- GEMM2 (reads SM_I) + store next tile (writes SM_T) ----
#pragma unroll
            for (int mf = 0; mf < 2; ++mf)
#pragma unroll
                for (int nf = 0; nf < 4; ++nf)
#pragma unroll
                    for (int q = 0; q < 4; ++q) acc[mf][nf][q] = 0.f;
            gemm_tile(sb, SM_I, SM_W + WPARTH, aR0, aR1, aR7, khA, bR0, bR1, bR7, khB, acc);

            if (havePref) store_tile(smem, SM_T, pref, tid);

            // ---- epi2: e_out writes ----
#pragma unroll
            for (int mf = 0; mf < 2; ++mf)
#pragma unroll
                for (int nf = 0; nf < 4; ++nf) {
                    int c = n0 + nf*8 + 2*t;
                    int jl = m0 + mf*16 + g;
                    size_t rb = OFF_EOUT + (((size_t)row)*N_ + j0 + jl)*H_ + c;
                    *(float2*)(out + rb) =
                        make_float2(acc[mf][nf][0] + bo2[nf].x, acc[mf][nf][1] + bo2[nf].y);
                    *(float2*)(out + rb + 8*H_) =
                        make_float2(acc[mf][nf][2] + bo2[nf].x, acc[mf][nf][3] + bo2[nf].y);
                }
            __syncthreads();   // B2: SM_T/SM_I handoff
        }

        // ---- fused mask + softmax: warp w handles head w ----
        {
            const float* lg = logit_s + wid * N_;
            const float* mrow = mask + ((size_t)b*N_ + i)*N_;
            float4 vv[4];
            float mx = -3.4e38f;
#pragma unroll
            for (int c4 = 0; c4 < 4; ++c4) {
                int j = c4*128 + lane*4;
                float4 lv = *(const float4*)(lg + j);
                float4 mv = *(const float4*)(mrow + j);
                float4 v = make_float4(lv.x + mv.x, lv.y + mv.y, lv.z + mv.z, lv.w + mv.w);
                vv[c4] = v;
                mx = fmaxf(mx, fmaxf(fmaxf(v.x, v.y), fmaxf(v.z, v.w)));
            }
#pragma unroll
            for (int o = 16; o > 0; o >>= 1)
                mx = fmaxf(mx, __shfl_xor_sync(0xffffffffu, mx, o));
            float sum = 0.f;
#pragma unroll
            for (int c4 = 0; c4 < 4; ++c4) {
                vv[c4].x = expf(vv[c4].x - mx);
                vv[c4].y = expf(vv[c4].y - mx);
                vv[c4].z = expf(vv[c4].z - mx);
                vv[c4].w = expf(vv[c4].w - mx);
                sum += vv[c4].x + vv[c4].y + vv[c4].z + vv[c4].w;
            }
#pragma unroll
            for (int o = 16; o > 0; o >>= 1)
                sum += __shfl_xor_sync(0xffffffffu, sum, o);
            float inv = 1.f / sum;
            float* orow = out + OFF_SCORES + (((size_t)(b*NH_ + wid)*N_ + i) << 9);
#pragma unroll
            for (int c4 = 0; c4 < 4; ++c4) {
                int j = c4*128 + lane*4;
                *(float4*)(orow + j) = make_float4(vv[c4].x*inv, vv[c4].y*inv,
                                                   vv[c4].z*inv, vv[c4].w*inv);
            }
        }
        __syncthreads();   // logit_s reads done before next row's epi1 writes
    }
}

// ---------------------------------------------------------------------------
// out: att = scores @ V(=K) ; x_out = att @ Woh + boh. (r9-measured variant)
// ---------------------------------------------------------------------------
__global__ __launch_bounds__(512)
void out_kernel(const float* __restrict__ Woh, const float* __restrict__ boh,
                float* __restrict__ out) {
    __shared__ float sc[2*NH_*N_];   // 32 KB
    __shared__ float red[2][512];
    __shared__ float att_s[2][H_];
    int blk = blockIdx.x;
    int b = blk >> 8, i0 = (blk & 255) << 1;
    int tid = threadIdx.x;

    const float* sp = out + OFF_SCORES;
    for (int u = tid; u < 2*NH_*N_; u += 512) {
        int il = u >> 12, h = (u >> 9) & 7, j = u & 511;
        sc[u] = sp[(((size_t)(b*NH_ + h)*N_ + i0 + il) << 9) + j];
    }
    __syncthreads();

    int c = tid & 127, t2 = tid >> 7;
    int h = c >> 4;
    const float* kp = g_K + (((size_t)b*N_) + t2*128)*H_ + c;
    const float* s0 = sc + h*N_ + t2*128;
    const float* s1 = sc + NH_*N_ + h*N_ + t2*128;
    float a0 = 0.f, a1 = 0.f;
#pragma unroll 8
    for (int j = 0; j < 128; ++j) {
        float kv = kp[(size_t)j*H_];
        a0 = fmaf(s0[j], kv, a0);
        a1 = fmaf(s1[j], kv, a1);
    }
    red[0][tid] = a0;
    red[1][tid] = a1;
    __syncthreads();
    if (tid < 256) {
        int il = tid >> 7, cc = tid & 127;
        att_s[il][cc] = red[il][cc] + red[il][128 + cc] +
                        red[il][256 + cc] + red[il][384 + cc];
    }
    __syncthreads();
    if (tid < 256) {
        int il = tid >> 7, cc = tid & 127;
        float o = boh[cc];
#pragma unroll 8
        for (int k = 0; k < H_; ++k)
            o = fmaf(att_s[il][k], Woh[k*H_ + cc], o);
        out[((size_t)(b*N_) + i0 + il)*H_ + cc] = o;
    }
}

// ---------------------------------------------------------------------------
extern "C" void kernel_launch(void* const* d_in, const int* in_sizes, int n_in,
                              void* d_out, int out_size) {
    const float* x    = (const float*)d_in[0];
    const float* e    = (const float*)d_in[1];
    const float* mask = (const float*)d_in[2];
    const float* Wq   = (const float*)d_in[3];
    const float* bq   = (const float*)d_in[4];
    const float* Wk   = (const float*)d_in[5];
    const float* bk   = (const float*)d_in[6];
    const float* We   = (const float*)d_in[7];
    const float* be   = (const float*)d_in[8];
    const float* Woh  = (const float*)d_in[9];
    const float* boh  = (const float*)d_in[10];
    const float* Woe  = (const float*)d_in[11];
    const float* boe  = (const float*)d_in[12];
    float* out = (float*)d_out;

    cudaFuncSetAttribute(edge_kernel, cudaFuncAttributeMaxDynamicSharedMemorySize, SM_TOTAL);

    prepqk_kernel<<<64 + NROW, 256>>>(We, Woe, be, boe, x, Wq, bq, Wk, bk);
    edge_kernel<<<148, 256, SM_TOTAL>>>(e, mask, out);
    out_kernel<<<NROW/2, 512>>>(Woh, boh, out);
}